// round 3
// baseline (speedup 1.0000x reference)
#include <cuda_runtime.h>
#include <cuda_bf16.h>

// RNN: B=8192, T=2048, I=2, H=20
//   h_{t+1} = tanh(x_t @ W_ih^T + b_ih + b_hh + h_t @ W_hh^T)
//   out = h_T @ fc_w^T + fc_b ; h_state = h_T
//
// Mapping: 4 threads per batch row; each thread owns 5 of the 20 hidden units
// and keeps its 5x20 slice of W_hh entirely in registers. The full h vector is
// exchanged each step via __shfl_sync within the 4-lane row group.
// x is cooperatively loaded (4 steps per float2-lane) and prefetched one
// chunk ahead.

#define BB 8192
#define TT 2048
#define HH 20
#define TPR 4   // threads per row
#define JPT 5   // hidden units per thread

__device__ __forceinline__ float tanh_fast(float a) {
    // tanh(a) = (e-1)/(e+1), e = exp(2a) = 2^(2a*log2(e))
    // ex2.approx + rcp.approx: ~1e-6 rel err, far better than tanh.approx.
    a = fminf(fmaxf(a, -12.0f), 12.0f);   // avoid inf/inf -> nan; tanh(12)=1-1e-10
    float e;
    asm("ex2.approx.f32 %0, %1;" : "=f"(e) : "f"(a * 2.8853900817779268f));
    float r;
    asm("rcp.approx.f32 %0, %1;" : "=f"(r) : "f"(e + 1.0f));
    return (e - 1.0f) * r;
}

__global__ __launch_bounds__(128)
void rnn_fused_kernel(const float* __restrict__ x,
                      const float* __restrict__ Wih,
                      const float* __restrict__ Whh,
                      const float* __restrict__ bih,
                      const float* __restrict__ bhh,
                      const float* __restrict__ fcw,
                      const float* __restrict__ fcb,
                      float* __restrict__ out) {
    const int tid  = blockIdx.x * blockDim.x + threadIdx.x;
    const int row  = tid >> 2;        // batch row
    const int part = tid & 3;         // which 5-unit slice
    const unsigned lane  = threadIdx.x & 31u;
    const unsigned gbase = lane & ~3u;  // base lane of this row's 4-lane group
    const unsigned FULL = 0xFFFFFFFFu;

    // ---- load per-thread constants into registers ----
    float W[JPT][HH];     // W_hh rows for my 5 outputs (100 regs)
    float bias[JPT], w0[JPT], w1[JPT];
#pragma unroll
    for (int jj = 0; jj < JPT; ++jj) {
        const int j = part * JPT + jj;
        bias[jj] = bih[j] + bhh[j];
        w0[jj] = Wih[2 * j];
        w1[jj] = Wih[2 * j + 1];
#pragma unroll
        for (int k = 0; k < HH; ++k) W[jj][k] = Whh[j * HH + k];
    }

    float h[JPT];
#pragma unroll
    for (int jj = 0; jj < JPT; ++jj) h[jj] = 0.0f;

    // x: [B, T, 2] -> as float2 per (row, t). Lane `part` holds steps 4c+part.
    const float2* xr = reinterpret_cast<const float2*>(x) + (size_t)row * TT;
    float2 xb = xr[part];             // chunk 0
    const int NC = TT / 4;            // 512 chunks

    for (int c = 0; c < NC; ++c) {
        // prefetch next chunk while computing this one
        float2 xn = make_float2(0.0f, 0.0f);
        if (c + 1 < NC) xn = xr[(c + 1) * 4 + part];

#pragma unroll
        for (int s = 0; s < 4; ++s) {
            const float x0 = __shfl_sync(FULL, xb.x, gbase + s);
            const float x1 = __shfl_sync(FULL, xb.y, gbase + s);

            float acc[JPT];
#pragma unroll
            for (int jj = 0; jj < JPT; ++jj)
                acc[jj] = fmaf(x1, w1[jj], fmaf(x0, w0[jj], bias[jj]));

#pragma unroll
            for (int k = 0; k < HH; ++k) {
                const float hk =
                    __shfl_sync(FULL, h[k % JPT], gbase + (unsigned)(k / JPT));
#pragma unroll
                for (int jj = 0; jj < JPT; ++jj)
                    acc[jj] = fmaf(hk, W[jj][k], acc[jj]);
            }
#pragma unroll
            for (int jj = 0; jj < JPT; ++jj) h[jj] = tanh_fast(acc[jj]);
        }
        xb = xn;
    }

    // ---- epilogue: fc head + h_state ----
    float p = 0.0f;
#pragma unroll
    for (int jj = 0; jj < JPT; ++jj)
        p = fmaf(h[jj], fcw[part * JPT + jj], p);
    p += __shfl_xor_sync(FULL, p, 1);
    p += __shfl_xor_sync(FULL, p, 2);
    if (part == 0) out[row] = p + fcb[0];

    float* hs = out + BB;  // h_state [1, B, H] right after out [B, 1]
#pragma unroll
    for (int jj = 0; jj < JPT; ++jj)
        hs[(size_t)row * HH + part * JPT + jj] = h[jj];
}

extern "C" void kernel_launch(void* const* d_in, const int* in_sizes, int n_in,
                              void* d_out, int out_size) {
    const float* x    = (const float*)d_in[0];
    const float* Wih  = (const float*)d_in[1];
    const float* Whh  = (const float*)d_in[2];
    const float* bih  = (const float*)d_in[3];
    const float* bhh  = (const float*)d_in[4];
    const float* fcw  = (const float*)d_in[5];
    const float* fcb  = (const float*)d_in[6];
    float* out = (float*)d_out;

    const int threads = BB * TPR;            // 32768
    rnn_fused_kernel<<<threads / 128, 128>>>(x, Wih, Whh, bih, bhh, fcw, fcb, out);
}